// round 4
// baseline (speedup 1.0000x reference)
#include <cuda_runtime.h>
#include <cuda_fp16.h>

#define MAXN 131072
#define HID 128

__device__ __half2 g_didx[MAXN];   // .x = dinv (fp16), .y = dx = dinv*x (fp16)
__device__ float   g_ssum[MAXN];
__device__ float   g_gsum[MAXN];
__device__ int     g_deg[MAXN];
__device__ float   g_v[HID];

__global__ void k_zero(int n) {
    int i = blockIdx.x * blockDim.x + threadIdx.x;
    if (i < n) g_deg[i] = 0;
    if (i < HID) g_v[i] = 0.0f;
}

// Pass 1: in-degree histogram over destinations
__global__ void k_deg(const int* __restrict__ col, int E) {
    int i = blockIdx.x * blockDim.x + threadIdx.x;
    if (i < E) atomicAdd(&g_deg[col[i]], 1);
}

// Pass 2: dinv = rsqrt(deg+1); pack {dinv, dinv*x} as half2; zero accumulators
__global__ void k_dinv(const float* __restrict__ x, int n) {
    int i = blockIdx.x * blockDim.x + threadIdx.x;
    if (i < n) {
        float di = rsqrtf((float)(g_deg[i] + 1));
        g_didx[i] = __floats2half2_rn(di, di * x[i]);
        g_ssum[i] = 0.0f;
        g_gsum[i] = 0.0f;
    }
}

// Pass 3: edge scatter, 1 edge/thread.
//   ssum[c] += dx[r]   (gather .y at r)
//   gsum[r] += dinv[c] (gather .x at c)
// Both gathers hit the SAME 200KB half2 array -> high sector reuse.
__global__ void k_scatter(const int* __restrict__ row,
                          const int* __restrict__ col, int E) {
    int i = blockIdx.x * blockDim.x + threadIdx.x;
    if (i < E) {
        int r = row[i];
        int c = col[i];
        __half2 hr = g_didx[r];
        __half2 hc = g_didx[c];
        atomicAdd(&g_ssum[c], __high2float(hr));   // dx[r]
        atomicAdd(&g_gsum[r], __low2float(hc));    // dinv[c]
    }
}

// Pass 4: v[f] = sum_r g[r] * relu(W1[f]*s[r] + b1[f])
//   s[r] = di*(ssum[r] + di*x[r])   (self-loop folded, di recomputed fp32)
//   g[r] = di*(gsum[r] + di)
__global__ void __launch_bounds__(HID) k_vred(const float* __restrict__ x,
                                              const float* __restrict__ W1,
                                              const float* __restrict__ b1,
                                              int n) {
    __shared__ float sh_s[HID];
    __shared__ float sh_g[HID];
    int f = threadIdx.x;
    float w  = W1[f];
    float bb = b1[f];
    float acc = 0.0f;

    for (int base = blockIdx.x * HID; base < n; base += gridDim.x * HID) {
        int r = base + f;
        float sv = 0.0f, gv = 0.0f;
        if (r < n) {
            float di = rsqrtf((float)(g_deg[r] + 1));
            sv = di * (g_ssum[r] + di * x[r]);
            gv = di * (g_gsum[r] + di);
        }
        __syncthreads();
        sh_s[f] = sv;
        sh_g[f] = gv;
        __syncthreads();
        int m = n - base; if (m > HID) m = HID;
        #pragma unroll 8
        for (int j = 0; j < m; j++) {
            acc += sh_g[j] * fmaxf(fmaf(w, sh_s[j], bb), 0.0f);
        }
    }
    atomicAdd(&g_v[f], acc);
}

// Pass 5: out[o] = b2[o] + (1/N) * sum_f v[f] * W2[f, o]
__global__ void k_out(const float* __restrict__ W2,
                      const float* __restrict__ b2,
                      float* __restrict__ out,
                      int out_dim, float inv_n) {
    int o = blockIdx.x * blockDim.x + threadIdx.x;
    if (o >= out_dim) return;
    float acc = 0.0f;
    #pragma unroll 8
    for (int f = 0; f < HID; f++) {
        acc += g_v[f] * W2[f * out_dim + o];
    }
    out[o] = b2[o] + acc * inv_n;
}

extern "C" void kernel_launch(void* const* d_in, const int* in_sizes, int n_in,
                              void* d_out, int out_size) {
    const float* x    = (const float*)d_in[0];        // [N,1]
    const int*   ei   = (const int*)  d_in[1];        // [2,E]
    const float* W1   = (const float*)d_in[2];        // [1,128]
    const float* b1   = (const float*)d_in[3];        // [128]
    const float* W2   = (const float*)d_in[4];        // [128,400]
    const float* b2   = (const float*)d_in[5];        // [400]
    float*       out  = (float*)d_out;                // [400]

    int N = in_sizes[0];
    int E = in_sizes[1] / 2;
    const int* row = ei;
    const int* col = ei + E;

    int tb = 256;
    k_zero<<<(N + tb - 1) / tb, tb>>>(N);
    k_deg<<<(E + tb - 1) / tb, tb>>>(col, E);
    k_dinv<<<(N + tb - 1) / tb, tb>>>(x, N);
    k_scatter<<<(E + tb - 1) / tb, tb>>>(row, col, E);
    k_vred<<<296, HID>>>(x, W1, b1, N);
    k_out<<<(out_size + 127) / 128, 128>>>(W2, b2, out, out_size, 1.0f / (float)N);
}

// round 5
// speedup vs baseline: 1.2607x; 1.2607x over previous
#include <cuda_runtime.h>

#define MAXN 131072
#define HID 128

__device__ float g_dinv[MAXN];
__device__ float g_dx[MAXN];
__device__ float g_ssum[MAXN];
__device__ float g_gsum[MAXN];
__device__ int   g_deg[MAXN];   // zero at module load; self-restored each run by k_dinv
__device__ float g_v[HID];      // zero at module load; self-restored each run by k_out

// Pass 1: in-degree histogram over destinations (deg starts zeroed)
__global__ void k_deg(const int2* __restrict__ col2, int E2,
                      const int* __restrict__ col, int E) {
    int i = blockIdx.x * blockDim.x + threadIdx.x;
    if (i < E2) {
        int2 c = col2[i];
        atomicAdd(&g_deg[c.x], 1);
        atomicAdd(&g_deg[c.y], 1);
    }
    if (i == 0 && (E & 1)) atomicAdd(&g_deg[col[E - 1]], 1);
}

// Pass 2: dinv = rsqrt(deg+1), dx = dinv*x ; zero accumulators ; reset deg
__global__ void k_dinv(const float* __restrict__ x, int n) {
    int i = blockIdx.x * blockDim.x + threadIdx.x;
    if (i < n) {
        int d = g_deg[i];
        g_deg[i] = 0;                       // restore for next replay
        float di = rsqrtf((float)(d + 1));
        g_dinv[i] = di;
        g_dx[i]   = di * x[i];
        g_ssum[i] = 0.0f;
        g_gsum[i] = 0.0f;
    }
}

// Pass 3: edge scatter, 2 edges/thread, SoA fp32 (R1 memory pattern).
//   ssum[c] += dx[r] ;  gsum[r] += dinv[c]
__global__ void k_scatter(const int2* __restrict__ row2,
                          const int2* __restrict__ col2, int E2,
                          const int* __restrict__ row,
                          const int* __restrict__ col, int E) {
    int i = blockIdx.x * blockDim.x + threadIdx.x;
    if (i < E2) {
        int2 r = row2[i];
        int2 c = col2[i];
        // batch gathers first for MLP
        float dx0 = g_dx[r.x];
        float dx1 = g_dx[r.y];
        float di0 = g_dinv[c.x];
        float di1 = g_dinv[c.y];
        atomicAdd(&g_ssum[c.x], dx0);
        atomicAdd(&g_ssum[c.y], dx1);
        atomicAdd(&g_gsum[r.x], di0);
        atomicAdd(&g_gsum[r.y], di1);
    }
    if (i == 0 && (E & 1)) {
        int rr = row[E - 1], cc = col[E - 1];
        atomicAdd(&g_ssum[cc], g_dx[rr]);
        atomicAdd(&g_gsum[rr], g_dinv[cc]);
    }
}

// Pass 4: v[f] = sum_r g[r] * relu(W1[f]*s[r] + b1[f])
//   s[r] = di*(ssum[r] + di*x[r]) = di*(ssum[r] + dx[r])
//   g[r] = di*(gsum[r] + di)
__global__ void __launch_bounds__(HID) k_vred(const float* __restrict__ W1,
                                              const float* __restrict__ b1,
                                              int n) {
    __shared__ float sh_s[HID];
    __shared__ float sh_g[HID];
    int f = threadIdx.x;
    float w  = W1[f];
    float bb = b1[f];
    float acc = 0.0f;

    for (int base = blockIdx.x * HID; base < n; base += gridDim.x * HID) {
        int r = base + f;
        float sv = 0.0f, gv = 0.0f;
        if (r < n) {
            float di = g_dinv[r];
            sv = di * (g_ssum[r] + g_dx[r]);
            gv = di * (g_gsum[r] + di);
        }
        __syncthreads();
        sh_s[f] = sv;
        sh_g[f] = gv;
        __syncthreads();
        int m = n - base; if (m > HID) m = HID;
        #pragma unroll 8
        for (int j = 0; j < m; j++) {
            acc += sh_g[j] * fmaxf(fmaf(w, sh_s[j], bb), 0.0f);
        }
    }
    atomicAdd(&g_v[f], acc);
}

// Pass 5 (single block): out[o] = b2[o] + (1/N)*sum_f v[f]*W2[f,o]; reset g_v.
__global__ void __launch_bounds__(512) k_out(const float* __restrict__ W2,
                                             const float* __restrict__ b2,
                                             float* __restrict__ out,
                                             int out_dim, float inv_n) {
    __shared__ float sv[HID];
    int t = threadIdx.x;
    if (t < HID) sv[t] = g_v[t];
    __syncthreads();
    for (int o = t; o < out_dim; o += blockDim.x) {
        float acc = 0.0f;
        #pragma unroll 16
        for (int f = 0; f < HID; f++) {
            acc += sv[f] * W2[f * out_dim + o];
        }
        out[o] = b2[o] + acc * inv_n;
    }
    __syncthreads();
    if (t < HID) g_v[t] = 0.0f;   // restore for next replay
}

extern "C" void kernel_launch(void* const* d_in, const int* in_sizes, int n_in,
                              void* d_out, int out_size) {
    const float* x    = (const float*)d_in[0];        // [N,1]
    const int*   ei   = (const int*)  d_in[1];        // [2,E]
    const float* W1   = (const float*)d_in[2];        // [1,128]
    const float* b1   = (const float*)d_in[3];        // [128]
    const float* W2   = (const float*)d_in[4];        // [128,400]
    const float* b2   = (const float*)d_in[5];        // [400]
    float*       out  = (float*)d_out;                // [400]

    int N  = in_sizes[0];
    int E  = in_sizes[1] / 2;
    const int* row = ei;
    const int* col = ei + E;
    int E2 = E / 2;

    int tb = 256;
    k_deg<<<(E2 + tb - 1) / tb, tb>>>((const int2*)col, E2, col, E);
    k_dinv<<<(N + tb - 1) / tb, tb>>>(x, N);
    k_scatter<<<(E2 + tb - 1) / tb, tb>>>((const int2*)row, (const int2*)col, E2,
                                          row, col, E);
    k_vred<<<296, HID>>>(W1, b1, N);
    k_out<<<1, 512>>>(W2, b2, out, out_size, 1.0f / (float)N);
}

// round 10
// speedup vs baseline: 1.3087x; 1.0381x over previous
#include <cuda_runtime.h>

#define MAXN 131072
#define HID 128

__device__ float g_dinv[MAXN];
__device__ float g_dx[MAXN];
__device__ float g_ssum[MAXN];
__device__ float g_gsum[MAXN];
__device__ int   g_deg[MAXN];   // zero at module load; self-restored by k_dinv
__device__ float g_v[HID];      // zero at module load; self-restored by k_out

// Pass 1: in-degree histogram over destinations (R1 scalar form)
__global__ void k_deg(const int* __restrict__ col, int E) {
    int i = blockIdx.x * blockDim.x + threadIdx.x;
    if (i < E) atomicAdd(&g_deg[col[i]], 1);
}

// Pass 2: dinv = rsqrt(deg+1), dx = dinv*x ; zero accumulators ; reset deg
__global__ void k_dinv(const float* __restrict__ x, int n) {
    int i = blockIdx.x * blockDim.x + threadIdx.x;
    if (i < n) {
        int d = g_deg[i];
        g_deg[i] = 0;                       // restore for next graph replay
        float di = rsqrtf((float)(d + 1));
        g_dinv[i] = di;
        g_dx[i]   = di * x[i];
        g_ssum[i] = 0.0f;
        g_gsum[i] = 0.0f;
    }
}

// Pass 3: edge scatter, 1 edge/thread, SoA fp32 (exact R1 memory pattern).
//   ssum[c] += dx[r] ;  gsum[r] += dinv[c]
__global__ void k_scatter(const int* __restrict__ row,
                          const int* __restrict__ col, int E) {
    int i = blockIdx.x * blockDim.x + threadIdx.x;
    if (i < E) {
        int r = row[i];
        int c = col[i];
        atomicAdd(&g_ssum[c], g_dx[r]);
        atomicAdd(&g_gsum[r], g_dinv[c]);
    }
}

// Pass 4: v[f] = sum_r g[r] * relu(W1[f]*s[r] + b1[f])
// One 128-node tile per block (grid = ceil(n/128)), 4-way ILP inner loop.
//   s[r] = di*(ssum[r] + dx[r]) ;  g[r] = di*(gsum[r] + di)
__global__ void __launch_bounds__(HID) k_vred(const float* __restrict__ W1,
                                              const float* __restrict__ b1,
                                              int n) {
    __shared__ float sh_s[HID];
    __shared__ float sh_g[HID];
    int f = threadIdx.x;
    int r = blockIdx.x * HID + f;

    float sv = 0.0f, gv = 0.0f;
    if (r < n) {
        float di = g_dinv[r];
        sv = di * (g_ssum[r] + g_dx[r]);
        gv = di * (g_gsum[r] + di);
    }
    sh_s[f] = sv;
    sh_g[f] = gv;
    __syncthreads();

    float w  = W1[f];
    float bb = b1[f];
    float a0 = 0.f, a1 = 0.f, a2 = 0.f, a3 = 0.f;
    #pragma unroll
    for (int j = 0; j < HID; j += 4) {
        a0 += sh_g[j + 0] * fmaxf(fmaf(w, sh_s[j + 0], bb), 0.0f);
        a1 += sh_g[j + 1] * fmaxf(fmaf(w, sh_s[j + 1], bb), 0.0f);
        a2 += sh_g[j + 2] * fmaxf(fmaf(w, sh_s[j + 2], bb), 0.0f);
        a3 += sh_g[j + 3] * fmaxf(fmaf(w, sh_s[j + 3], bb), 0.0f);
    }
    atomicAdd(&g_v[f], (a0 + a1) + (a2 + a3));
}

// Pass 5 (single block): out[o] = b2[o] + (1/N)*sum_f v[f]*W2[f,o]; reset g_v.
__global__ void __launch_bounds__(512) k_out(const float* __restrict__ W2,
                                             const float* __restrict__ b2,
                                             float* __restrict__ out,
                                             int out_dim, float inv_n) {
    __shared__ float sv[HID];
    int t = threadIdx.x;
    if (t < HID) sv[t] = g_v[t];
    __syncthreads();
    for (int o = t; o < out_dim; o += blockDim.x) {
        float acc = 0.0f;
        #pragma unroll 16
        for (int f = 0; f < HID; f++) {
            acc += sv[f] * W2[f * out_dim + o];
        }
        out[o] = b2[o] + acc * inv_n;
    }
    __syncthreads();
    if (t < HID) g_v[t] = 0.0f;   // restore for next replay
}

extern "C" void kernel_launch(void* const* d_in, const int* in_sizes, int n_in,
                              void* d_out, int out_size) {
    const float* x    = (const float*)d_in[0];        // [N,1]
    const int*   ei   = (const int*)  d_in[1];        // [2,E]
    const float* W1   = (const float*)d_in[2];        // [1,128]
    const float* b1   = (const float*)d_in[3];        // [128]
    const float* W2   = (const float*)d_in[4];        // [128,400]
    const float* b2   = (const float*)d_in[5];        // [400]
    float*       out  = (float*)d_out;                // [400]

    int N = in_sizes[0];
    int E = in_sizes[1] / 2;
    const int* row = ei;
    const int* col = ei + E;

    int tb = 256;
    int ntile = (N + HID - 1) / HID;
    k_deg<<<(E + tb - 1) / tb, tb>>>(col, E);
    k_dinv<<<(N + tb - 1) / tb, tb>>>(x, N);
    k_scatter<<<(E + tb - 1) / tb, tb>>>(row, col, E);
    k_vred<<<ntile, HID>>>(W1, b1, N);
    k_out<<<1, 512>>>(W2, b2, out, out_size, 1.0f / (float)N);
}